// round 1
// baseline (speedup 1.0000x reference)
#include <cuda_runtime.h>
#include <math.h>

#define BATCH 4

// ---------------- scratch (static device arrays; no allocation) ----------------
__device__ float g_xd0[BATCH*1104*10*32];
__device__ float g_cat1[BATCH*1488*20*64];
__device__ float g_xd1[BATCH*552*20*64];
__device__ float g_ll1[BATCH*20*64];
__device__ float g_h1[BATCH*3*20*64];
__device__ float g_ll40[BATCH*40*128];
__device__ float g_mask1[BATCH*20*64];
__device__ float g_upm1[BATCH*20*64];
__device__ float g_cam1[BATCH*40*128];
__device__ float g_wm1[BATCH*40*128];
__device__ float g_feat1[BATCH*744*40*128];
__device__ float g_xa[BATCH*276*40*128];
__device__ float g_h2[BATCH*3*40*128];
__device__ float g_ll80[BATCH*80*256];
__device__ float g_mask2[BATCH*40*128];
__device__ float g_upm2[BATCH*40*128];
__device__ float g_cam2[BATCH*80*256];
__device__ float g_wm2[BATCH*80*256];
__device__ float g_feat0[BATCH*372*80*256];
__device__ float g_xb[BATCH*138*80*256];
__device__ float g_h3[BATCH*3*80*256];
__device__ float g_thr[1];

// ---------------- big conv: 64 OC x (8 rows x 16 cols) tile, 128 threads -------
// thread computes 8 oc x 8 px.  PAD: 0=zero, 1=reflect, 2=edge(replicate)
template<int PAD>
__global__ __launch_bounds__(128)
void conv3x3_big(const float* __restrict__ in, const float* __restrict__ wgt,
                 const float* __restrict__ bias, float* __restrict__ out,
                 int IC, int OC, int H, int W,
                 int leaky, const float* __restrict__ mask)
{
    __shared__ float sW[64*72];    // [oc_local][ic_local*9+t]
    __shared__ float sX[8*190];    // [ic_local][10 rows x 19(pad) cols]

    const int tid  = threadIdx.x;
    const int ocg  = tid >> 4;          // 0..7  (8 oc each)
    const int pxg  = tid & 15;          // 0..15 (8 px each)
    const int trow = pxg >> 1;          // 0..7
    const int tcol = (pxg & 1) << 3;    // 0 or 8

    const int tilesX = W >> 4;
    const int tx = blockIdx.x % tilesX;
    const int ty = blockIdx.x / tilesX;
    const int row0 = ty << 3;
    const int col0 = tx << 4;
    const int oc0  = blockIdx.y << 6;
    const int b    = blockIdx.z;

    const float* inb = in + (size_t)b*IC*H*W;
    const size_t K9 = (size_t)IC*9;

    float acc[8][8];
    #pragma unroll
    for (int j=0;j<8;j++)
        #pragma unroll
        for (int i=0;i<8;i++) acc[j][i]=0.f;

    for (int ic0=0; ic0<IC; ic0+=8) {
        // ---- load input tile: 8 ic x 10 x 18 (with padding resolved here) ----
        for (int i = tid; i < 1440; i += 128) {
            int ici = i / 180;
            int rem = i - ici*180;
            int r = rem / 18;
            int c = rem - r*18;
            int gy = row0 - 1 + r;
            int gx = col0 - 1 + c;
            float v = 0.f;
            int ic = ic0 + ici;
            if (ic < IC) {
                int yy = gy, xx = gx;
                bool ok = true;
                if (PAD == 0) {
                    ok = (gy>=0) && (gy<H) && (gx>=0) && (gx<W);
                } else if (PAD == 1) {
                    yy = gy < 0 ? -gy : (gy >= H ? 2*H-2-gy : gy);
                    xx = gx < 0 ? -gx : (gx >= W ? 2*W-2-gx : gx);
                } else {
                    yy = min(max(gy,0),H-1);
                    xx = min(max(gx,0),W-1);
                }
                if (ok) v = __ldg(inb + (size_t)ic*H*W + yy*W + xx);
            }
            sX[ici*190 + r*19 + c] = v;
        }
        // ---- load weights: 64 oc x (8 ic x 9) ----
        {
            const float* wbase = wgt + (size_t)oc0*K9 + (size_t)ic0*9;
            const int kmax = (int)(K9 - (size_t)ic0*9);
            for (int i = tid; i < 4608; i += 128) {
                int ocl = i / 72;
                int k   = i - ocl*72;
                float v = 0.f;
                if ((oc0+ocl) < OC && k < kmax)
                    v = __ldg(wbase + (size_t)ocl*K9 + k);
                sW[ocl*72 + k] = v;
            }
        }
        __syncthreads();

        #pragma unroll 2
        for (int ici=0; ici<8; ici++) {
            #pragma unroll
            for (int t=0;t<9;t++) {
                const int dy = t/3, dx = t%3;
                float xv[8];
                const float* xp = &sX[ici*190 + (trow+dy)*19 + tcol + dx];
                #pragma unroll
                for (int i=0;i<8;i++) xv[i] = xp[i];
                const float* wp = &sW[(ocg<<3)*72 + ici*9 + t];
                #pragma unroll
                for (int j=0;j<8;j++) {
                    float wv = wp[j*72];
                    #pragma unroll
                    for (int i=0;i<8;i++) acc[j][i] = fmaf(wv, xv[i], acc[j][i]);
                }
            }
        }
        __syncthreads();
    }

    // ---- epilogue: +bias, leaky, optional per-pixel mask ----
    const int orow = row0 + trow;
    if (orow >= H) return;
    #pragma unroll
    for (int j=0;j<8;j++) {
        int oc = oc0 + (ocg<<3) + j;
        if (oc >= OC) break;
        float bv = __ldg(bias + oc);
        float* op = out + ((size_t)b*OC + oc)*H*W + (size_t)orow*W + col0 + tcol;
        #pragma unroll
        for (int i=0;i<8;i++) {
            float v = acc[j][i] + bv;
            if (leaky) v = v > 0.f ? v : 0.2f*v;
            if (mask)  v *= mask[(size_t)b*H*W + (size_t)orow*W + col0 + tcol + i];
            op[i] = v;
        }
    }
}

// ---------------- small conv (OC<=3): thread per pixel ----------------
// maskcoarse: mask sampled at (y/2, x/2) on an H/2 x W/2 grid
template<int NOUT, int PAD>
__global__ void conv3x3_small(const float* __restrict__ in, const float* __restrict__ wgt,
                              const float* __restrict__ bias, float* __restrict__ out,
                              int IC, int H, int W, float scale,
                              const float* __restrict__ mask, int maskcoarse)
{
    int b = blockIdx.z;
    int p = blockIdx.x*blockDim.x + threadIdx.x;
    if (p >= H*W) return;
    int y = p / W, x = p - y*W;
    float acc[NOUT];
    #pragma unroll
    for (int j=0;j<NOUT;j++) acc[j]=0.f;
    const float* inb = in + (size_t)b*IC*H*W;
    for (int ic=0; ic<IC; ic++) {
        const float* ip = inb + (size_t)ic*H*W;
        const float* wp = wgt + (size_t)ic*9;
        #pragma unroll
        for (int t=0;t<9;t++) {
            int yy = y + t/3 - 1, xx = x + t%3 - 1;
            float v;
            if (PAD == 0) {
                v = (yy>=0 && yy<H && xx>=0 && xx<W) ? __ldg(ip + yy*W + xx) : 0.f;
            } else { // edge
                yy = min(max(yy,0),H-1); xx = min(max(xx,0),W-1);
                v = __ldg(ip + yy*W + xx);
            }
            #pragma unroll
            for (int j=0;j<NOUT;j++)
                acc[j] = fmaf(v, __ldg(wp + (size_t)j*IC*9 + t), acc[j]);
        }
    }
    float mval = 1.f;
    if (mask) {
        if (maskcoarse) mval = mask[(size_t)b*(H/2)*(W/2) + (size_t)(y>>1)*(W/2) + (x>>1)];
        else            mval = mask[(size_t)b*H*W + p];
    }
    #pragma unroll
    for (int j=0;j<NOUT;j++)
        out[((size_t)b*NOUT + j)*H*W + p] = (acc[j] + __ldg(bias + j)) * scale * mval;
}

// ---------------- inverse Haar DWT ----------------
__global__ void idwt_k(const float* __restrict__ ll, const float* __restrict__ h,
                       float* __restrict__ out, int Hc, int Wc)
{
    int b = blockIdx.z;
    int p = blockIdx.x*256 + threadIdx.x;
    if (p >= Hc*Wc) return;
    int y = p / Wc, x = p - y*Wc;
    float l  = ll[(size_t)b*Hc*Wc + p];
    const float* hb = h + (size_t)b*3*Hc*Wc;
    float lh = hb[p], hl = hb[Hc*Wc + p], hh = hb[2*Hc*Wc + p];
    float a  = (l + lh)*0.5f, c2 = (l - lh)*0.5f;
    float d2 = (hl + hh)*0.5f, e = (hl - hh)*0.5f;
    float* ob = out + (size_t)b*(2*Hc)*(2*Wc);
    int W2 = 2*Wc;
    ob[(size_t)(2*y)*W2   + 2*x]   = a + d2;
    ob[(size_t)(2*y)*W2   + 2*x+1] = c2 + e;
    ob[(size_t)(2*y+1)*W2 + 2*x]   = a - d2;
    ob[(size_t)(2*y+1)*W2 + 2*x+1] = c2 - e;
}

// ---------------- global (max-min)*0.1 -> thr[0], single block ----------------
__global__ void minmax_k(const float* __restrict__ d, int n, float* __restrict__ thr)
{
    __shared__ float smn[1024], smx[1024];
    int tid = threadIdx.x;
    float mn = 3.4e38f, mx = -3.4e38f;
    for (int i = tid; i < n; i += 1024) { float v = d[i]; mn = fminf(mn,v); mx = fmaxf(mx,v); }
    smn[tid]=mn; smx[tid]=mx; __syncthreads();
    for (int s=512; s>0; s>>=1) {
        if (tid < s) { smn[tid]=fminf(smn[tid],smn[tid+s]); smx[tid]=fmaxf(smx[tid],smx[tid+s]); }
        __syncthreads();
    }
    if (tid==0) thr[0] = (smx[0]-smn[0])*0.1f;
}

// ---------------- mask = (max_c |h_c| > thr) ----------------
__global__ void mask_k(const float* __restrict__ h, const float* __restrict__ thr,
                       float* __restrict__ mask, int Hc, int Wc)
{
    int b = blockIdx.z;
    int p = blockIdx.x*256 + threadIdx.x;
    if (p >= Hc*Wc) return;
    const float* hb = h + (size_t)b*3*Hc*Wc;
    float m = fmaxf(fabsf(hb[p]), fmaxf(fabsf(hb[Hc*Wc+p]), fabsf(hb[2*Hc*Wc+p])));
    mask[(size_t)b*Hc*Wc + p] = (m > thr[0]) ? 1.f : 0.f;
}

// ---------------- 5x5 SAME maxpool>0 on coarse mask ----------------
__global__ void pool_coarse_k(const float* __restrict__ mask, float* __restrict__ upm,
                              int Hc, int Wc)
{
    int b = blockIdx.z;
    int p = blockIdx.x*256 + threadIdx.x;
    if (p >= Hc*Wc) return;
    int y = p / Wc, x = p - y*Wc;
    const float* mb = mask + (size_t)b*Hc*Wc;
    float r = 0.f;
    for (int dy=-2;dy<=2;dy++){ int yy=y+dy; if (yy<0||yy>=Hc) continue;
      for (int dx=-2;dx<=2;dx++){ int xx=x+dx; if (xx<0||xx>=Wc) continue;
        r = fmaxf(r, mb[yy*Wc+xx]); } }
    upm[(size_t)b*Hc*Wc + p] = (r > 0.f) ? 1.f : 0.f;
}

// ---------------- maxpool5>0 and maxpool3>0 over up2x(mask), at fine res ------
__global__ void pool_fine_k(const float* __restrict__ mask, float* __restrict__ cam,
                            float* __restrict__ wm, int Hc, int Wc)
{
    int b = blockIdx.z;
    int Hf = 2*Hc, Wf = 2*Wc;
    int p = blockIdx.x*256 + threadIdx.x;
    if (p >= Hf*Wf) return;
    int y = p / Wf, x = p - y*Wf;
    const float* mb = mask + (size_t)b*Hc*Wc;
    float c5 = 0.f, c3 = 0.f;
    for (int dy=-2;dy<=2;dy++){ int fy=y+dy; if (fy<0||fy>=Hf) continue;
      for (int dx=-2;dx<=2;dx++){ int fx=x+dx; if (fx<0||fx>=Wf) continue;
        float v = mb[(fy>>1)*Wc + (fx>>1)];
        c5 = fmaxf(c5, v);
        if (dy>=-1 && dy<=1 && dx>=-1 && dx<=1) c3 = fmaxf(c3, v);
      } }
    cam[(size_t)b*Hf*Wf + p] = (c5 > 0.f) ? 1.f : 0.f;
    wm [(size_t)b*Hf*Wf + p] = (c3 > 0.f) ? 1.f : 0.f;
}

// ---------------- feat build: cat(up2x(xc * upm), skip) * cam ----------------
__global__ void feat_k(const float* __restrict__ xc, const float* __restrict__ skip,
                       const float* __restrict__ upm, const float* __restrict__ cam,
                       float* __restrict__ out, int C1, int C2, int Hf, int Wf, int total)
{
    int idx = blockIdx.x*256 + threadIdx.x;
    if (idx >= total) return;
    int Wc = Wf >> 1, Hc = Hf >> 1;
    int x = idx % Wf; int t = idx / Wf;
    int y = t % Hf;  t /= Hf;
    int c = t % (C1+C2); int b = t / (C1+C2);
    float v;
    if (c < C1) {
        size_t ci = ((size_t)b*C1 + c)*Hc*Wc + (size_t)(y>>1)*Wc + (x>>1);
        v = xc[ci];
        if (upm) v *= upm[(size_t)b*Hc*Wc + (size_t)(y>>1)*Wc + (x>>1)];
    } else {
        v = skip[((size_t)b*C2 + (c-C1))*Hf*Wf + (size_t)y*Wf + x];
    }
    if (cam) v *= cam[(size_t)b*Hf*Wf + (size_t)y*Wf + x];
    out[idx] = v;
}

// =======================================================================
extern "C" void kernel_launch(void* const* d_in, const int* in_sizes, int n_in,
                              void* d_out, int out_size)
{
    const float* x32      = (const float*)d_in[0];
    const float* x16      = (const float*)d_in[1];
    const float* x8       = (const float*)d_in[2];
    const float* x4       = (const float*)d_in[3];
    const float* conv2_w  = (const float*)d_in[4];
    const float* conv2_b  = (const float*)d_in[5];
    const float* up1_w    = (const float*)d_in[6];
    const float* up1_b    = (const float*)d_in[7];
    const float* w1ll_w   = (const float*)d_in[8];
    const float* w1ll_b   = (const float*)d_in[9];
    const float* w1_w     = (const float*)d_in[10];
    const float* w1_b     = (const float*)d_in[11];
    const float* up2_w    = (const float*)d_in[12];
    const float* up2_b    = (const float*)d_in[13];
    const float* w2_w     = (const float*)d_in[14];
    const float* w2_b     = (const float*)d_in[15];
    const float* up3_w    = (const float*)d_in[16];
    const float* up3_b    = (const float*)d_in[17];
    const float* w3_w     = (const float*)d_in[18];
    const float* w3_b     = (const float*)d_in[19];

    float *xd0,*cat1,*xd1,*ll1,*h1,*ll40,*mask1,*upm1,*cam1,*wm1;
    float *feat1,*xa,*h2,*ll80,*mask2,*upm2,*cam2,*wm2,*feat0,*xb,*h3,*thr;
    cudaGetSymbolAddress((void**)&xd0,  g_xd0);
    cudaGetSymbolAddress((void**)&cat1, g_cat1);
    cudaGetSymbolAddress((void**)&xd1,  g_xd1);
    cudaGetSymbolAddress((void**)&ll1,  g_ll1);
    cudaGetSymbolAddress((void**)&h1,   g_h1);
    cudaGetSymbolAddress((void**)&ll40, g_ll40);
    cudaGetSymbolAddress((void**)&mask1,g_mask1);
    cudaGetSymbolAddress((void**)&upm1, g_upm1);
    cudaGetSymbolAddress((void**)&cam1, g_cam1);
    cudaGetSymbolAddress((void**)&wm1,  g_wm1);
    cudaGetSymbolAddress((void**)&feat1,g_feat1);
    cudaGetSymbolAddress((void**)&xa,   g_xa);
    cudaGetSymbolAddress((void**)&h2,   g_h2);
    cudaGetSymbolAddress((void**)&ll80, g_ll80);
    cudaGetSymbolAddress((void**)&mask2,g_mask2);
    cudaGetSymbolAddress((void**)&upm2, g_upm2);
    cudaGetSymbolAddress((void**)&cam2, g_cam2);
    cudaGetSymbolAddress((void**)&wm2,  g_wm2);
    cudaGetSymbolAddress((void**)&feat0,g_feat0);
    cudaGetSymbolAddress((void**)&xb,   g_xb);
    cudaGetSymbolAddress((void**)&h3,   g_h3);
    cudaGetSymbolAddress((void**)&thr,  g_thr);

    // 1) conv2: 2208 -> 1104, 10x32, edge pad
    conv3x3_big<2><<<dim3(2*2, 18, BATCH), 128>>>(x32, conv2_w, conv2_b, xd0,
                                                  2208, 1104, 10, 32, 0, nullptr);
    // 2) cat1 = concat(up2x(xd0), x16)  -> [4,1488,20,64]
    {
        int total = BATCH*1488*20*64;
        feat_k<<<(total+255)/256, 256>>>(xd0, x16, nullptr, nullptr, cat1,
                                         1104, 384, 20, 64, total);
    }
    // 3) up1: 1488 -> 552, 20x64, reflect, leaky
    conv3x3_big<1><<<dim3(4*3, 9, BATCH), 128>>>(cat1, up1_w, up1_b, xd1,
                                                 1488, 552, 20, 64, 1, nullptr);
    // 4) wave1ll: 8*conv (edge), 5) wave1: 4*conv (zero)
    conv3x3_small<1,2><<<dim3(5,1,BATCH), 256>>>(xd1, w1ll_w, w1ll_b, ll1,
                                                 552, 20, 64, 8.f, nullptr, 0);
    conv3x3_small<3,0><<<dim3(5,1,BATCH), 256>>>(xd1, w1_w, w1_b, h1,
                                                 552, 20, 64, 4.f, nullptr, 0);
    // 6) idwt -> ll40 [4,1,40,128]
    idwt_k<<<dim3(5,1,BATCH), 256>>>(ll1, h1, ll40, 20, 64);
    // 7) thresh from ll40
    minmax_k<<<1, 1024>>>(ll40, BATCH*40*128, thr);
    // 8) mask1 (20x64) from h1
    mask_k<<<dim3(5,1,BATCH), 256>>>(h1, thr, mask1, 20, 64);
    // 9) pooled masks
    pool_coarse_k<<<dim3(5,1,BATCH), 256>>>(mask1, upm1, 20, 64);
    pool_fine_k  <<<dim3(20,1,BATCH), 256>>>(mask1, cam1, wm1, 20, 64);
    // 10) feat1 = cat(up2x(xd1*upm1), x8) * cam1 -> [4,744,40,128]
    {
        int total = BATCH*744*40*128;
        feat_k<<<(total+255)/256, 256>>>(xd1, x8, upm1, cam1, feat1,
                                         552, 192, 40, 128, total);
    }
    // 11) up2: 744 -> 276, 40x128, reflect, leaky, * wm1
    conv3x3_big<1><<<dim3(8*5, 5, BATCH), 128>>>(feat1, up2_w, up2_b, xa,
                                                 744, 276, 40, 128, 1, wm1);
    // 12) h2 = 2*conv(xa) * up2x(mask1)
    conv3x3_small<3,0><<<dim3(20,1,BATCH), 256>>>(xa, w2_w, w2_b, h2,
                                                  276, 40, 128, 2.f, mask1, 1);
    // 13) idwt -> ll80
    idwt_k<<<dim3(20,1,BATCH), 256>>>(ll40, h2, ll80, 40, 128);
    // 14) thresh from ll80
    minmax_k<<<1, 1024>>>(ll80, BATCH*80*256, thr);
    // 15) mask2 (40x128) from h2
    mask_k<<<dim3(20,1,BATCH), 256>>>(h2, thr, mask2, 40, 128);
    // 16) pooled masks level 0
    pool_coarse_k<<<dim3(20,1,BATCH), 256>>>(mask2, upm2, 40, 128);
    pool_fine_k  <<<dim3(80,1,BATCH), 256>>>(mask2, cam2, wm2, 40, 128);
    // 17) feat0 = cat(up2x(xa*upm2), x4) * cam2 -> [4,372,80,256]
    {
        int total = BATCH*372*80*256;
        feat_k<<<(total+255)/256, 256>>>(xa, x4, upm2, cam2, feat0,
                                         276, 96, 80, 256, total);
    }
    // 18) up3: 372 -> 138, 80x256, reflect, leaky, * wm2
    conv3x3_big<1><<<dim3(16*10, 3, BATCH), 128>>>(feat0, up3_w, up3_b, xb,
                                                   372, 138, 80, 256, 1, wm2);
    // 19) h3 = conv(xb) * up2x(mask2)
    conv3x3_small<3,0><<<dim3(80,1,BATCH), 256>>>(xb, w3_w, w3_b, h3,
                                                  138, 80, 256, 1.f, mask2, 1);
    // 20) final idwt -> d_out [4,1,160,512]
    idwt_k<<<dim3(80,1,BATCH), 256>>>(ll80, h3, (float*)d_out, 80, 256);
}